// round 5
// baseline (speedup 1.0000x reference)
#include <cuda_runtime.h>

#define H_DIM 512
#define W_DIM 512
#define RPB   8       // output rows per block
#define NTHREADS 128  // 4 px/thread * 128 threads = 512 columns = full row
#define MAX_BLOCKS 8192

__device__ float    g_part[MAX_BLOCKS];
__device__ unsigned g_ticket;   // zero-init; restored to 0 by last block each run

// ---------- packed f32x2 helpers: pairs are ADJACENT PIXELS of one image ----
typedef unsigned long long u64;

__device__ __forceinline__ u64 pk2(float lo, float hi) {
    u64 r; asm("mov.b64 %0, {%1, %2};" : "=l"(r) : "f"(lo), "f"(hi)); return r;
}
__device__ __forceinline__ void upk2(u64 v, float& lo, float& hi) {
    asm("mov.b64 {%0, %1}, %2;" : "=f"(lo), "=f"(hi) : "l"(v));
}
__device__ __forceinline__ u64 add2(u64 a, u64 b) {
    u64 d; asm("add.rn.f32x2 %0, %1, %2;" : "=l"(d) : "l"(a), "l"(b)); return d;
}
__device__ __forceinline__ u64 sub2(u64 a, u64 b) {
    u64 d; asm("sub.rn.f32x2 %0, %1, %2;" : "=l"(d) : "l"(a), "l"(b)); return d;
}
__device__ __forceinline__ u64 mul2(u64 a, u64 b) {
    u64 d; asm("mul.rn.f32x2 %0, %1, %2;" : "=l"(d) : "l"(a), "l"(b)); return d;
}
__device__ __forceinline__ u64 fma2(u64 a, u64 b, u64 c) {
    u64 d; asm("fma.rn.f32x2 %0, %1, %2, %3;" : "=l"(d) : "l"(a), "l"(b), "l"(c)); return d;
}
__device__ __forceinline__ u64 abs2(u64 a) {   // packed |x| via sign-mask
    u64 d; asm("and.b64 %0, %1, 0x7FFFFFFF7FFFFFFF;" : "=l"(d) : "l"(a)); return d;
}
__device__ __forceinline__ u64 rsq2(u64 a) {   // packed rsqrt (2x MUFU)
    float lo, hi; upk2(a, lo, hi);
    return pk2(rsqrtf(lo), rsqrtf(hi));
}

struct PConsts { u64 two, one, c3, c0, ca, cb; };

// Per-row Sobel pieces for 4 px as two packed pairs (01, 23), one image:
//   d = val(x-1) - val(x+1) ; s = val(x-1) + 2 val(x) + val(x+1)
struct RowP { u64 d01, d23, s01, s23; };

__device__ __forceinline__ RowP row_pack(const float* __restrict__ img,
                                         int x0, int xm, int xp, const PConsts& K) {
    float4 v = *reinterpret_cast<const float4*>(img + x0);
    float hm = __ldg(img + xm);
    float hp = __ldg(img + xp);
    u64 p01 = pk2(v.x, v.y);   // natural pair from the float4 load
    u64 p23 = pk2(v.z, v.w);   // natural pair
    u64 a   = pk2(hm, v.x);    // shifted pair (x-1 of px0, px1)
    u64 b   = pk2(v.y, v.z);   // shifted pair (x+1 of px0, px1) == (x-1 of px2, px3)
    u64 c   = pk2(v.w, hp);    // shifted pair (x+1 of px2, px3)
    RowP r;
    r.d01 = sub2(a, b);
    r.d23 = sub2(b, c);
    r.s01 = add2(fma2(K.two, p01, a), b);
    r.s23 = add2(fma2(K.two, p23, b), c);
    return r;
}

// Packed normal for a pixel pair of ONE image:
//   q = gx^2+gy^2, u = 1-q, v = 0.0625 + 3.9375q, r = rsqrt(u*v)
//   nx = gx*su*r, ny = gy*su*r, 4*nz = u*r   (su ~ sqrt(1-q), 2-term poly)
__device__ __forceinline__ void normal_pack(u64 dp, u64 dc, u64 dn, u64 sp, u64 sn,
                                            const PConsts& K,
                                            u64& nx, u64& ny, u64& ur) {
    u64 gx = add2(fma2(K.two, dc, dp), dn);
    u64 gy = sub2(sp, sn);
    u64 q  = fma2(gx, gx, mul2(gy, gy));
    u64 u  = sub2(K.one, q);
    u64 v  = fma2(K.c3, q, K.c0);
    u64 r  = rsq2(mul2(u, v));
    u64 su = fma2(q, fma2(q, K.ca, K.cb), K.one);
    u64 il = mul2(su, r);
    nx = mul2(gx, il);
    ny = mul2(gy, il);
    ur = mul2(u, r);           // 4*nz ; 0.25 applied once at the very end
}

__global__ void __launch_bounds__(NTHREADS, 8)
heightmap_loss_kernel(const float* __restrict__ gen, const float* __restrict__ tgt,
                      float* __restrict__ out, double inv_n) {
    const int b    = blockIdx.y;
    const int y0   = blockIdx.x * RPB;
    const int lane = threadIdx.x & 31;
    const int x0   = threadIdx.x * 4;
    const int xm   = max(x0 - 1, 0);
    const int xp   = min(x0 + 4, W_DIM - 1);
    const int nblocks = gridDim.x * gridDim.y;
    const int bid     = blockIdx.y * gridDim.x + blockIdx.x;

    PConsts K;
    K.two = pk2(2.f, 2.f);
    K.one = pk2(1.f, 1.f);
    K.c3  = pk2(3.9375f, 3.9375f);
    K.c0  = pk2(0.0625f, 0.0625f);
    K.ca  = pk2(-0.125f, -0.125f);
    K.cb  = pk2(-0.5f, -0.5f);

    const float* __restrict__ gimg = gen + (size_t)b * (H_DIM * W_DIM);
    const float* __restrict__ timg = tgt + (size_t)b * (H_DIM * W_DIM);

    // rolling 3-row window (prev, cur, next) per image
    RowP gP, gC, gN, tP, tC, tN;
    {
        int ym = max(y0 - 1, 0);
        gP = row_pack(gimg + ym * W_DIM, x0, xm, xp, K);
        tP = row_pack(timg + ym * W_DIM, x0, xm, xp, K);
        gC = row_pack(gimg + y0 * W_DIM, x0, xm, xp, K);
        tC = row_pack(timg + y0 * W_DIM, x0, xm, xp, K);
    }

    u64 accxy = 0;   // packed sum of |dnx|+|dny| over pixel pairs
    u64 accz  = 0;   // packed sum of |d(4nz)|
    #pragma unroll
    for (int yy = 0; yy < RPB; yy++) {
        int yn = min(y0 + yy + 1, H_DIM - 1);
        gN = row_pack(gimg + yn * W_DIM, x0, xm, xp, K);
        tN = row_pack(timg + yn * W_DIM, x0, xm, xp, K);

        u64 gnx, gny, gur, tnx, tny, tur;
        // pair 01
        normal_pack(gP.d01, gC.d01, gN.d01, gP.s01, gN.s01, K, gnx, gny, gur);
        normal_pack(tP.d01, tC.d01, tN.d01, tP.s01, tN.s01, K, tnx, tny, tur);
        accxy = add2(accxy, add2(abs2(sub2(gnx, tnx)), abs2(sub2(gny, tny))));
        accz  = add2(accz, abs2(sub2(gur, tur)));
        // pair 23
        normal_pack(gP.d23, gC.d23, gN.d23, gP.s23, gN.s23, K, gnx, gny, gur);
        normal_pack(tP.d23, tC.d23, tN.d23, tP.s23, tN.s23, K, tnx, tny, tur);
        accxy = add2(accxy, add2(abs2(sub2(gnx, tnx)), abs2(sub2(gny, tny))));
        accz  = add2(accz, abs2(sub2(gur, tur)));

        gP = gC; gC = gN;
        tP = tC; tC = tN;
    }

    float al, ah, zl, zh;
    upk2(accxy, al, ah);
    upk2(accz,  zl, zh);
    float acc = fmaf(0.25f, zl + zh, al + ah);

    // warp reduce
    #pragma unroll
    for (int o = 16; o > 0; o >>= 1)
        acc += __shfl_down_sync(0xffffffffu, acc, o);

    __shared__ float ws[NTHREADS / 32];
    __shared__ bool  isLast;
    if (lane == 0) ws[threadIdx.x >> 5] = acc;
    __syncthreads();
    if (threadIdx.x == 0) {
        g_part[bid] = ws[0] + ws[1] + ws[2] + ws[3];
        __threadfence();
        unsigned prev = atomicAdd(&g_ticket, 1u);
        isLast = (prev == (unsigned)(nblocks - 1));
    }
    __syncthreads();

    // Last block to finish performs the deterministic final reduction.
    if (isLast) {
        double s = 0.0;
        for (int i = threadIdx.x; i < nblocks; i += NTHREADS)
            s += (double)g_part[i];
        #pragma unroll
        for (int o = 16; o > 0; o >>= 1)
            s += __shfl_down_sync(0xffffffffu, s, o);
        __shared__ double ds[NTHREADS / 32];
        if (lane == 0) ds[threadIdx.x >> 5] = s;
        __syncthreads();
        if (threadIdx.x == 0) {
            double t = ds[0] + ds[1] + ds[2] + ds[3];
            out[0] = (float)(t * inv_n);
            g_ticket = 0u;   // restore invariant for graph replay
        }
    }
}

extern "C" void kernel_launch(void* const* d_in, const int* in_sizes, int n_in,
                              void* d_out, int out_size) {
    const float* gen = (const float*)d_in[0];
    const float* tgt = (const float*)d_in[1];
    float* out = (float*)d_out;

    const int total = in_sizes[0];              // B*1*H*W
    const int B = total / (H_DIM * W_DIM);

    dim3 grid(H_DIM / RPB, B);
    heightmap_loss_kernel<<<grid, NTHREADS>>>(gen, tgt, out,
                                              1.0 / (3.0 * (double)total));
}

// round 6
// speedup vs baseline: 1.0694x; 1.0694x over previous
#include <cuda_runtime.h>

#define H_DIM 512
#define W_DIM 512
#define RPB   8       // output rows per block
#define NTHREADS 128  // 4 px/thread * 128 threads = 512 columns = full row
#define MAX_BLOCKS 8192

__device__ float    g_part[MAX_BLOCKS];
__device__ unsigned g_ticket;   // zero-init; restored to 0 by last block each run

// Per-row separable Sobel pieces for 4 consecutive pixels:
//   d[j] = val(x-1) - val(x+1)            (horizontal part of SOBEL_X)
//   s[j] = val(x-1) + 2*val(x) + val(x+1) (horizontal part of SOBEL_Y)
struct DS { float dx, dy, dz, dw, sx, sy, sz, sw; };

// Halo via two clamped scalar LDGs (L1 hits) — no SHFL, no lane predicates.
__device__ __forceinline__ DS row_ds(const float* __restrict__ row,
                                     int x0, int xm, int xp) {
    float4 v  = *reinterpret_cast<const float4*>(row + x0);
    float xm1 = __ldg(row + xm);
    float xp4 = __ldg(row + xp);
    DS r;
    r.dx = xm1 - v.y;  r.dy = v.x - v.z;  r.dz = v.y - v.w;  r.dw = v.z - xp4;
    r.sx = fmaf(2.f, v.x, xm1) + v.y;
    r.sy = fmaf(2.f, v.y, v.x) + v.z;
    r.sz = fmaf(2.f, v.z, v.y) + v.w;
    r.sw = fmaf(2.f, v.w, v.z) + xp4;
    return r;
}

// Normal from (gx, gy), single MUFU.RSQ:
//   q = gx^2+gy^2, u = 1-q, v = 0.0625 + 3.9375q (= 4q + (1-q)/16)
//   r = rsqrt(u*v)  =>  4*nz = u*r ;  1/length = sqrt(u)*r
//   sqrt(u) ~= 1 - q/2 - q^2/8  (q <= 0.08 -> err < 4e-5; typical q~5e-3 -> ~1e-8)
//   Returns nx, ny, and ur = 4*nz (0.25 folded into final accumulation).
__device__ __forceinline__ void normal3(float gx, float gy,
                                        float& nx, float& ny, float& ur) {
    float q  = fmaf(gx, gx, gy * gy);
    float u  = 1.f - q;
    float v  = fmaf(3.9375f, q, 0.0625f);
    float r  = rsqrtf(u * v);
    float su = fmaf(q, fmaf(q, -0.125f, -0.5f), 1.f);  // ~sqrt(1-q)
    float il = su * r;          // 1/length
    nx = gx * il;
    ny = gy * il;
    ur = u * r;                 // 4*nz
}

// Accumulates |dnx|+|dny| into axy and |d(4nz)| into az.
__device__ __forceinline__ void contrib(
    float dpg, float dcg, float dng, float spg, float sng,
    float dpt, float dct, float dnt, float spt, float snt,
    float& axy, float& az) {
    float gxg = fmaf(2.f, dcg, dpg) + dng;
    float gyg = spg - sng;
    float gxt = fmaf(2.f, dct, dpt) + dnt;
    float gyt = spt - snt;
    float nxg, nyg, urg, nxt, nyt, urt;
    normal3(gxg, gyg, nxg, nyg, urg);
    normal3(gxt, gyt, nxt, nyt, urt);
    axy += fabsf(nxg - nxt) + fabsf(nyg - nyt);
    az  += fabsf(urg - urt);
}

__global__ void __launch_bounds__(NTHREADS, 8)
heightmap_loss_kernel(const float* __restrict__ gen, const float* __restrict__ tgt,
                      float* __restrict__ out, double inv_n) {
    const int b    = blockIdx.y;
    const int y0   = blockIdx.x * RPB;
    const int lane = threadIdx.x & 31;
    const int x0   = threadIdx.x * 4;
    const int xm   = max(x0 - 1, 0);
    const int xp   = min(x0 + 4, W_DIM - 1);
    const int nblocks = gridDim.x * gridDim.y;
    const int bid     = blockIdx.y * gridDim.x + blockIdx.x;

    const float* __restrict__ gimg = gen + (size_t)b * (H_DIM * W_DIM);
    const float* __restrict__ timg = tgt + (size_t)b * (H_DIM * W_DIM);

    // rolling 3-row window (prev, cur, next) per image
    DS gP, gC, gN, tP, tC, tN;
    {
        int ym = max(y0 - 1, 0);
        gP = row_ds(gimg + ym * W_DIM, x0, xm, xp);
        tP = row_ds(timg + ym * W_DIM, x0, xm, xp);
        gC = row_ds(gimg + y0 * W_DIM, x0, xm, xp);
        tC = row_ds(timg + y0 * W_DIM, x0, xm, xp);
    }

    float axy = 0.f, az = 0.f;
    #pragma unroll
    for (int yy = 0; yy < RPB; yy++) {
        int yn = min(y0 + yy + 1, H_DIM - 1);
        gN = row_ds(gimg + yn * W_DIM, x0, xm, xp);
        tN = row_ds(timg + yn * W_DIM, x0, xm, xp);

        contrib(gP.dx, gC.dx, gN.dx, gP.sx, gN.sx,
                tP.dx, tC.dx, tN.dx, tP.sx, tN.sx, axy, az);
        contrib(gP.dy, gC.dy, gN.dy, gP.sy, gN.sy,
                tP.dy, tC.dy, tN.dy, tP.sy, tN.sy, axy, az);
        contrib(gP.dz, gC.dz, gN.dz, gP.sz, gN.sz,
                tP.dz, tC.dz, tN.dz, tP.sz, tN.sz, axy, az);
        contrib(gP.dw, gC.dw, gN.dw, gP.sw, gN.sw,
                tP.dw, tC.dw, tN.dw, tP.sw, tN.sw, axy, az);

        gP = gC; gC = gN;
        tP = tC; tC = tN;
    }

    float acc = fmaf(0.25f, az, axy);

    // warp reduce
    #pragma unroll
    for (int o = 16; o > 0; o >>= 1)
        acc += __shfl_down_sync(0xffffffffu, acc, o);

    __shared__ float ws[NTHREADS / 32];
    __shared__ bool  isLast;
    if (lane == 0) ws[threadIdx.x >> 5] = acc;
    __syncthreads();
    if (threadIdx.x == 0) {
        g_part[bid] = ws[0] + ws[1] + ws[2] + ws[3];
        __threadfence();
        unsigned prev = atomicAdd(&g_ticket, 1u);
        isLast = (prev == (unsigned)(nblocks - 1));
    }
    __syncthreads();

    // Last block to finish performs the deterministic final reduction.
    if (isLast) {
        double s = 0.0;
        for (int i = threadIdx.x; i < nblocks; i += NTHREADS)
            s += (double)g_part[i];
        #pragma unroll
        for (int o = 16; o > 0; o >>= 1)
            s += __shfl_down_sync(0xffffffffu, s, o);
        __shared__ double ds[NTHREADS / 32];
        if (lane == 0) ds[threadIdx.x >> 5] = s;
        __syncthreads();
        if (threadIdx.x == 0) {
            double t = ds[0] + ds[1] + ds[2] + ds[3];
            out[0] = (float)(t * inv_n);
            g_ticket = 0u;   // restore invariant for graph replay
        }
    }
}

extern "C" void kernel_launch(void* const* d_in, const int* in_sizes, int n_in,
                              void* d_out, int out_size) {
    const float* gen = (const float*)d_in[0];
    const float* tgt = (const float*)d_in[1];
    float* out = (float*)d_out;

    const int total = in_sizes[0];              // B*1*H*W
    const int B = total / (H_DIM * W_DIM);

    dim3 grid(H_DIM / RPB, B);
    heightmap_loss_kernel<<<grid, NTHREADS>>>(gen, tgt, out,
                                              1.0 / (3.0 * (double)total));
}